// round 4
// baseline (speedup 1.0000x reference)
#include <cuda_runtime.h>
#include <math.h>

// Shapes (fixed by the problem)
#define S_LEN 96
#define B_SZ  32
#define I_DIM 64
#define H_DIM 256
#define M_ALL (S_LEN * B_SZ)      // 3072
#define NELEM (M_ALL * H_DIM)     // 786432 per (S,B,H) slab

// Scratch (device globals: no allocation allowed in kernel_launch)
__device__ float g_fx[NELEM];   // x @ W_fx^T + b_fx   (S,B,H)
__device__ float g_cx[NELEM];   // x @ W_cx^T + b_cx   (S,B,H)
__device__ float g_hhA[NELEM];  // hh ping
__device__ float g_hhB[NELEM];  // hh pong
__device__ float g_cc[NELEM];   // cell state

// ---------------------------------------------------------------------------
// Zero-init: hh(read buffer of step 0) and cc must start at 0 every call.
// ---------------------------------------------------------------------------
__global__ void zero_kernel() {
    int i = blockIdx.x * blockDim.x + threadIdx.x;
    if (i < NELEM / 4) {
        float4 z = make_float4(0.f, 0.f, 0.f, 0.f);
        reinterpret_cast<float4*>(g_hhA)[i] = z;
        reinterpret_cast<float4*>(g_cc)[i]  = z;
    }
}

// ---------------------------------------------------------------------------
// Precompute fx and cx:  (3072 x 64) @ (256 x 64)^T, two weights share x.
// Tile 64x64, K=64 processed in two 32-chunks, 256 threads, 4x4 micro-tile.
// ---------------------------------------------------------------------------
__global__ __launch_bounds__(256) void pre_kernel(
    const float* __restrict__ x,
    const float* __restrict__ W_fx, const float* __restrict__ b_fx,
    const float* __restrict__ W_cx, const float* __restrict__ b_cx)
{
    __shared__ __align__(16) float Xs[32][68];  // [k][m]
    __shared__ __align__(16) float Wf[32][68];  // [k][n]
    __shared__ __align__(16) float Wc[32][68];  // [k][n]

    const int tid = threadIdx.x;
    const int bm = blockIdx.x * 64;
    const int bn = blockIdx.y * 64;
    const int m0 = (tid & 15) * 4;
    const int n0 = (tid >> 4) * 4;

    float uf[4][4] = {};
    float uc[4][4] = {};

    for (int c = 0; c < 2; ++c) {
        if (c) __syncthreads();           // protect smem reuse
        const int k0 = c * 32;
        #pragma unroll
        for (int l = 0; l < 2; ++l) {
            int idx = tid + l * 256;       // 512 float4 per tile
            int row = idx >> 3;            // 0..63
            int seg = idx & 7;             // 0..7 -> 4 k's each
            float4 xa = *reinterpret_cast<const float4*>(&x   [(bm + row) * I_DIM + k0 + seg * 4]);
            float4 wa = *reinterpret_cast<const float4*>(&W_fx[(bn + row) * I_DIM + k0 + seg * 4]);
            float4 wb = *reinterpret_cast<const float4*>(&W_cx[(bn + row) * I_DIM + k0 + seg * 4]);
            int kb = seg * 4;
            Xs[kb+0][row] = xa.x; Xs[kb+1][row] = xa.y; Xs[kb+2][row] = xa.z; Xs[kb+3][row] = xa.w;
            Wf[kb+0][row] = wa.x; Wf[kb+1][row] = wa.y; Wf[kb+2][row] = wa.z; Wf[kb+3][row] = wa.w;
            Wc[kb+0][row] = wb.x; Wc[kb+1][row] = wb.y; Wc[kb+2][row] = wb.z; Wc[kb+3][row] = wb.w;
        }
        __syncthreads();
        #pragma unroll
        for (int kk = 0; kk < 32; ++kk) {
            float a[4], f[4], g[4];
            *reinterpret_cast<float4*>(a) = *reinterpret_cast<const float4*>(&Xs[kk][m0]);
            *reinterpret_cast<float4*>(f) = *reinterpret_cast<const float4*>(&Wf[kk][n0]);
            *reinterpret_cast<float4*>(g) = *reinterpret_cast<const float4*>(&Wc[kk][n0]);
            #pragma unroll
            for (int i = 0; i < 4; ++i)
                #pragma unroll
                for (int j = 0; j < 4; ++j) {
                    uf[i][j] += a[i] * f[j];
                    uc[i][j] += a[i] * g[j];
                }
        }
    }

    float bf[4], bc[4];
    *reinterpret_cast<float4*>(bf) = *reinterpret_cast<const float4*>(&b_fx[bn + n0]);
    *reinterpret_cast<float4*>(bc) = *reinterpret_cast<const float4*>(&b_cx[bn + n0]);
    #pragma unroll
    for (int i = 0; i < 4; ++i) {
        int m = bm + m0 + i;
        float of[4], oc[4];
        #pragma unroll
        for (int j = 0; j < 4; ++j) {
            of[j] = uf[i][j] + bf[j];
            oc[j] = uc[i][j] + bc[j];
        }
        *reinterpret_cast<float4*>(&g_fx[m * H_DIM + bn + n0]) = *reinterpret_cast<float4*>(of);
        *reinterpret_cast<float4*>(&g_cx[m * H_DIM + bn + n0]) = *reinterpret_cast<float4*>(oc);
    }
}

// ---------------------------------------------------------------------------
// One recurrence step (launched 96x, sequentially in-stream):
//   u = hh_in @ W_fh^T, v = hh_in @ W_ch^T (shared A, fused),
//   g = sigmoid(fx[t,b,:] + u + b_fh), cand = tanh(cx + v + b_ch),
//   cc = g*(cc + cand), hh_out = g*tanh(cc), h_seq[t] = hh_out.
// Tile 64(M) x 32(N), K=256 in 16-chunks, double-buffered smem, 128 threads.
// hh ping-pongs between g_hhA/g_hhB (CTAs read full hh rows others write).
// ---------------------------------------------------------------------------
__global__ __launch_bounds__(128) void step_kernel(
    const float* __restrict__ W_fh, const float* __restrict__ b_fh,
    const float* __restrict__ W_ch, const float* __restrict__ b_ch,
    float* __restrict__ out, int t)
{
    __shared__ __align__(16) float As[2][16][68];  // [buf][k][m]
    __shared__ __align__(16) float Bf[2][16][36];  // [buf][k][n]
    __shared__ __align__(16) float Bc[2][16][36];

    const float* __restrict__ hin  = (t & 1) ? g_hhB : g_hhA;
    float*       __restrict__ hout = (t & 1) ? g_hhA : g_hhB;

    const int tid = threadIdx.x;
    const int bm = blockIdx.x * 64;
    const int bn = blockIdx.y * 32;
    const int m0 = (tid & 15) * 4;    // 0..60
    const int n0 = (tid >> 4) * 4;    // 0..28
    const int lrow = tid >> 2;        // 0..31
    const int lseg = tid & 3;         // 0..3

    float u[4][4] = {};
    float v[4][4] = {};

    float4 ra0, ra1, rbf, rbc;

    // prologue: load + stage chunk 0
    ra0 = *reinterpret_cast<const float4*>(&hin [(bm + lrow)      * H_DIM + lseg * 4]);
    ra1 = *reinterpret_cast<const float4*>(&hin [(bm + lrow + 32) * H_DIM + lseg * 4]);
    rbf = *reinterpret_cast<const float4*>(&W_fh[(bn + lrow)      * H_DIM + lseg * 4]);
    rbc = *reinterpret_cast<const float4*>(&W_ch[(bn + lrow)      * H_DIM + lseg * 4]);
    {
        int kb = lseg * 4;
        As[0][kb+0][lrow]    = ra0.x; As[0][kb+1][lrow]    = ra0.y; As[0][kb+2][lrow]    = ra0.z; As[0][kb+3][lrow]    = ra0.w;
        As[0][kb+0][lrow+32] = ra1.x; As[0][kb+1][lrow+32] = ra1.y; As[0][kb+2][lrow+32] = ra1.z; As[0][kb+3][lrow+32] = ra1.w;
        Bf[0][kb+0][lrow]    = rbf.x; Bf[0][kb+1][lrow]    = rbf.y; Bf[0][kb+2][lrow]    = rbf.z; Bf[0][kb+3][lrow]    = rbf.w;
        Bc[0][kb+0][lrow]    = rbc.x; Bc[0][kb+1][lrow]    = rbc.y; Bc[0][kb+2][lrow]    = rbc.z; Bc[0][kb+3][lrow]    = rbc.w;
    }
    __syncthreads();

    #pragma unroll 1
    for (int c = 0; c < 16; ++c) {
        const int p = c & 1;
        if (c < 15) {
            int kc0 = (c + 1) * 16;
            ra0 = *reinterpret_cast<const float4*>(&hin [(bm + lrow)      * H_DIM + kc0 + lseg * 4]);
            ra1 = *reinterpret_cast<const float4*>(&hin [(bm + lrow + 32) * H_DIM + kc0 + lseg * 4]);
            rbf = *reinterpret_cast<const float4*>(&W_fh[(bn + lrow)      * H_DIM + kc0 + lseg * 4]);
            rbc = *reinterpret_cast<const float4*>(&W_ch[(bn + lrow)      * H_DIM + kc0 + lseg * 4]);
        }
        #pragma unroll
        for (int kk = 0; kk < 16; ++kk) {
            float a[4], f[4], g2[4];
            *reinterpret_cast<float4*>(a)  = *reinterpret_cast<const float4*>(&As[p][kk][m0]);
            *reinterpret_cast<float4*>(f)  = *reinterpret_cast<const float4*>(&Bf[p][kk][n0]);
            *reinterpret_cast<float4*>(g2) = *reinterpret_cast<const float4*>(&Bc[p][kk][n0]);
            #pragma unroll
            for (int i = 0; i < 4; ++i)
                #pragma unroll
                for (int j = 0; j < 4; ++j) {
                    u[i][j] += a[i] * f[j];
                    v[i][j] += a[i] * g2[j];
                }
        }
        if (c < 15) {
            const int q = p ^ 1;     // chunk c-1's buffer: already fully consumed
            int kb = lseg * 4;
            As[q][kb+0][lrow]    = ra0.x; As[q][kb+1][lrow]    = ra0.y; As[q][kb+2][lrow]    = ra0.z; As[q][kb+3][lrow]    = ra0.w;
            As[q][kb+0][lrow+32] = ra1.x; As[q][kb+1][lrow+32] = ra1.y; As[q][kb+2][lrow+32] = ra1.z; As[q][kb+3][lrow+32] = ra1.w;
            Bf[q][kb+0][lrow]    = rbf.x; Bf[q][kb+1][lrow]    = rbf.y; Bf[q][kb+2][lrow]    = rbf.z; Bf[q][kb+3][lrow]    = rbf.w;
            Bc[q][kb+0][lrow]    = rbc.x; Bc[q][kb+1][lrow]    = rbc.y; Bc[q][kb+2][lrow]    = rbc.z; Bc[q][kb+3][lrow]    = rbc.w;
        }
        __syncthreads();
    }

    // ---- fused gate epilogue ----
    float bfh[4], bch[4];
    *reinterpret_cast<float4*>(bfh) = *reinterpret_cast<const float4*>(&b_fh[bn + n0]);
    *reinterpret_cast<float4*>(bch) = *reinterpret_cast<const float4*>(&b_ch[bn + n0]);

    float* hseq = out + (size_t)t * NELEM;
    const int last = (t == S_LEN - 1);

    #pragma unroll
    for (int i = 0; i < 4; ++i) {
        const int m  = bm + m0 + i;
        const int bb = m & (B_SZ - 1);          // batch index (m = s*B + b)
        const int off = m * H_DIM + bn + n0;

        float fx4[4], cx4[4], cc4[4];
        *reinterpret_cast<float4*>(fx4) = *reinterpret_cast<const float4*>(&g_fx[(t * B_SZ + bb) * H_DIM + bn + n0]);
        *reinterpret_cast<float4*>(cx4) = *reinterpret_cast<const float4*>(&g_cx[off]);
        *reinterpret_cast<float4*>(cc4) = *reinterpret_cast<const float4*>(&g_cc[off]);

        float hn[4], cn[4];
        #pragma unroll
        for (int j = 0; j < 4; ++j) {
            float gate = 1.f / (1.f + expf(-(fx4[j] + u[i][j] + bfh[j])));
            float cand = tanhf(cx4[j] + v[i][j] + bch[j]);
            float c2   = gate * (cc4[j] + cand);   // forget gate == input gate (ref bug)
            cn[j] = c2;
            hn[j] = gate * tanhf(c2);              // output gate == g (ref bug)
        }
        *reinterpret_cast<float4*>(&g_cc[off]) = *reinterpret_cast<float4*>(cn);
        *reinterpret_cast<float4*>(&hout[off]) = *reinterpret_cast<float4*>(hn);
        *reinterpret_cast<float4*>(&hseq[off]) = *reinterpret_cast<float4*>(hn);
        if (last) {
            // h_fin == h_seq[S-1], c_fin == final cc
            *reinterpret_cast<float4*>(&out[(size_t)S_LEN * NELEM + off])       = *reinterpret_cast<float4*>(hn);
            *reinterpret_cast<float4*>(&out[(size_t)(S_LEN + 1) * NELEM + off]) = *reinterpret_cast<float4*>(cn);
        }
    }
}

// ---------------------------------------------------------------------------
// Launch: init -> input projections -> 96 sequential fused steps.
// Inputs (metadata order): x, W_fx, b_fx, W_fh, b_fh, W_cx, b_cx, W_ch, b_ch
// Output: [h_seq (S,S,B,H) | h_fin (S,B,H) | c_fin (S,B,H)] flattened.
// ---------------------------------------------------------------------------
extern "C" void kernel_launch(void* const* d_in, const int* in_sizes, int n_in,
                              void* d_out, int out_size)
{
    const float* x    = (const float*)d_in[0];
    const float* W_fx = (const float*)d_in[1];
    const float* b_fx = (const float*)d_in[2];
    const float* W_fh = (const float*)d_in[3];
    const float* b_fh = (const float*)d_in[4];
    const float* W_cx = (const float*)d_in[5];
    const float* b_cx = (const float*)d_in[6];
    const float* W_ch = (const float*)d_in[7];
    const float* b_ch = (const float*)d_in[8];
    float* out = (float*)d_out;

    zero_kernel<<<(NELEM / 4 + 255) / 256, 256>>>();
    pre_kernel<<<dim3(M_ALL / 64, H_DIM / 64), 256>>>(x, W_fx, b_fx, W_cx, b_cx);

    dim3 grid(M_ALL / 64, H_DIM / 32);   // 48 x 8 = 384 CTAs
    for (int t = 0; t < S_LEN; ++t) {
        step_kernel<<<grid, 128>>>(W_fh, b_fh, W_ch, b_ch, out, t);
    }
}

// round 5
// speedup vs baseline: 1.0346x; 1.0346x over previous
#include <cuda_runtime.h>
#include <math.h>

// Shapes (fixed by the problem)
#define S_LEN 96
#define B_SZ  32
#define I_DIM 64
#define H_DIM 256
#define M_ALL (S_LEN * B_SZ)      // 3072
#define NELEM (M_ALL * H_DIM)     // 786432 per (S,B,H) slab

typedef unsigned long long u64;

// Scratch (device globals: no allocation allowed in kernel_launch)
__device__ float g_fx[NELEM];   // x @ W_fx^T + b_fx   (S,B,H)
__device__ float g_cx[NELEM];   // x @ W_cx^T + b_cx   (S,B,H)
__device__ float g_hhA[NELEM];  // hh ping
__device__ float g_hhB[NELEM];  // hh pong
__device__ float g_cc[NELEM];   // cell state

// ---------------------------------------------------------------------------
// Packed f32x2 helpers (Blackwell FFMA2 via PTX; per-lane RN rounding ==
// identical numerics to scalar FFMA).
// ---------------------------------------------------------------------------
__device__ __forceinline__ u64 ffma2(u64 a, u64 b, u64 c) {
    u64 d;
    asm("fma.rn.f32x2 %0, %1, %2, %3;" : "=l"(d) : "l"(a), "l"(b), "l"(c));
    return d;
}
__device__ __forceinline__ u64 pack2(float x) {
    u64 r;
    asm("mov.b64 %0, {%1, %1};" : "=l"(r) : "r"(__float_as_uint(x)));
    return r;
}
__device__ __forceinline__ float2 unpack2(u64 v) {
    unsigned lo, hi;
    asm("mov.b64 {%0, %1}, %2;" : "=r"(lo), "=r"(hi) : "l"(v));
    return make_float2(__uint_as_float(lo), __uint_as_float(hi));
}

// Fast transcendentals (abs err ~1e-7; gate is 1e-3 rel on the whole output)
__device__ __forceinline__ float fast_sigmoid(float z) {
    return 1.f / (1.f + __expf(-z));
}
__device__ __forceinline__ float fast_tanh(float x) {
    float e = __expf(2.f * fabsf(x));         // overflow -> inf -> r = 1
    float r = 1.f - __fdividef(2.f, e + 1.f);
    return copysignf(r, x);
}

// ---------------------------------------------------------------------------
// Zero-init: hh(read buffer of step 0) and cc must start at 0 every call.
// ---------------------------------------------------------------------------
__global__ void zero_kernel() {
    int i = blockIdx.x * blockDim.x + threadIdx.x;
    if (i < NELEM / 4) {
        float4 z = make_float4(0.f, 0.f, 0.f, 0.f);
        reinterpret_cast<float4*>(g_hhA)[i] = z;
        reinterpret_cast<float4*>(g_cc)[i]  = z;
    }
}

// ---------------------------------------------------------------------------
// Precompute fx and cx:  (3072 x 64) @ (256 x 64)^T, two weights share x.
// ---------------------------------------------------------------------------
__global__ __launch_bounds__(256) void pre_kernel(
    const float* __restrict__ x,
    const float* __restrict__ W_fx, const float* __restrict__ b_fx,
    const float* __restrict__ W_cx, const float* __restrict__ b_cx)
{
    __shared__ __align__(16) float Xs[32][68];  // [k][m]
    __shared__ __align__(16) float Wf[32][68];  // [k][n]
    __shared__ __align__(16) float Wc[32][68];  // [k][n]

    const int tid = threadIdx.x;
    const int bm = blockIdx.x * 64;
    const int bn = blockIdx.y * 64;
    const int m0 = (tid & 15) * 4;
    const int n0 = (tid >> 4) * 4;

    float uf[4][4] = {};
    float uc[4][4] = {};

    for (int c = 0; c < 2; ++c) {
        if (c) __syncthreads();
        const int k0 = c * 32;
        #pragma unroll
        for (int l = 0; l < 2; ++l) {
            int idx = tid + l * 256;
            int row = idx >> 3;
            int seg = idx & 7;
            float4 xa = *reinterpret_cast<const float4*>(&x   [(bm + row) * I_DIM + k0 + seg * 4]);
            float4 wa = *reinterpret_cast<const float4*>(&W_fx[(bn + row) * I_DIM + k0 + seg * 4]);
            float4 wb = *reinterpret_cast<const float4*>(&W_cx[(bn + row) * I_DIM + k0 + seg * 4]);
            int kb = seg * 4;
            Xs[kb+0][row] = xa.x; Xs[kb+1][row] = xa.y; Xs[kb+2][row] = xa.z; Xs[kb+3][row] = xa.w;
            Wf[kb+0][row] = wa.x; Wf[kb+1][row] = wa.y; Wf[kb+2][row] = wa.z; Wf[kb+3][row] = wa.w;
            Wc[kb+0][row] = wb.x; Wc[kb+1][row] = wb.y; Wc[kb+2][row] = wb.z; Wc[kb+3][row] = wb.w;
        }
        __syncthreads();
        #pragma unroll
        for (int kk = 0; kk < 32; ++kk) {
            float a[4], f[4], g[4];
            *reinterpret_cast<float4*>(a) = *reinterpret_cast<const float4*>(&Xs[kk][m0]);
            *reinterpret_cast<float4*>(f) = *reinterpret_cast<const float4*>(&Wf[kk][n0]);
            *reinterpret_cast<float4*>(g) = *reinterpret_cast<const float4*>(&Wc[kk][n0]);
            #pragma unroll
            for (int i = 0; i < 4; ++i)
                #pragma unroll
                for (int j = 0; j < 4; ++j) {
                    uf[i][j] += a[i] * f[j];
                    uc[i][j] += a[i] * g[j];
                }
        }
    }

    float bf[4], bc[4];
    *reinterpret_cast<float4*>(bf) = *reinterpret_cast<const float4*>(&b_fx[bn + n0]);
    *reinterpret_cast<float4*>(bc) = *reinterpret_cast<const float4*>(&b_cx[bn + n0]);
    #pragma unroll
    for (int i = 0; i < 4; ++i) {
        int m = bm + m0 + i;
        float of[4], oc[4];
        #pragma unroll
        for (int j = 0; j < 4; ++j) {
            of[j] = uf[i][j] + bf[j];
            oc[j] = uc[i][j] + bc[j];
        }
        *reinterpret_cast<float4*>(&g_fx[m * H_DIM + bn + n0]) = *reinterpret_cast<float4*>(of);
        *reinterpret_cast<float4*>(&g_cx[m * H_DIM + bn + n0]) = *reinterpret_cast<float4*>(oc);
    }
}

// ---------------------------------------------------------------------------
// One recurrence step (launched 96x):
//   u = hh_in @ W_fh^T, v = hh_in @ W_ch^T (shared A, fused),
//   g = sigmoid(fx[t,b,:] + u + b_fh), cand = tanh(cx + v + b_ch),
//   cc = g*(cc + cand), hh_out = g*tanh(cc), h_seq[t] = hh_out.
// Tile 64(M) x 32(N), K=256 in 16-chunks, double-buffered smem, 128 threads.
// Inner product done with packed fma.rn.f32x2 (2 fp32 MACs / instruction).
// ---------------------------------------------------------------------------
__global__ __launch_bounds__(128) void step_kernel(
    const float* __restrict__ W_fh, const float* __restrict__ b_fh,
    const float* __restrict__ W_ch, const float* __restrict__ b_ch,
    float* __restrict__ out, int t)
{
    __shared__ __align__(16) float As[2][16][68];  // [buf][k][m]
    __shared__ __align__(16) float Bf[2][16][36];  // [buf][k][n]
    __shared__ __align__(16) float Bc[2][16][36];

    const float* __restrict__ hin  = (t & 1) ? g_hhB : g_hhA;
    float*       __restrict__ hout = (t & 1) ? g_hhA : g_hhB;

    const int tid = threadIdx.x;
    const int bm = blockIdx.x * 64;
    const int bn = blockIdx.y * 32;
    const int m0 = (tid & 15) * 4;    // 0..60
    const int n0 = (tid >> 4) * 4;    // 0..28
    const int lrow = tid >> 2;        // 0..31
    const int lseg = tid & 3;         // 0..3

    // packed accumulators: u2[i][jp] holds (u[i][2jp], u[i][2jp+1])
    u64 u2[4][2] = {};
    u64 v2[4][2] = {};

    float4 ra0, ra1, rbf, rbc;

    // prologue: load + stage chunk 0
    ra0 = *reinterpret_cast<const float4*>(&hin [(bm + lrow)      * H_DIM + lseg * 4]);
    ra1 = *reinterpret_cast<const float4*>(&hin [(bm + lrow + 32) * H_DIM + lseg * 4]);
    rbf = *reinterpret_cast<const float4*>(&W_fh[(bn + lrow)      * H_DIM + lseg * 4]);
    rbc = *reinterpret_cast<const float4*>(&W_ch[(bn + lrow)      * H_DIM + lseg * 4]);
    {
        int kb = lseg * 4;
        As[0][kb+0][lrow]    = ra0.x; As[0][kb+1][lrow]    = ra0.y; As[0][kb+2][lrow]    = ra0.z; As[0][kb+3][lrow]    = ra0.w;
        As[0][kb+0][lrow+32] = ra1.x; As[0][kb+1][lrow+32] = ra1.y; As[0][kb+2][lrow+32] = ra1.z; As[0][kb+3][lrow+32] = ra1.w;
        Bf[0][kb+0][lrow]    = rbf.x; Bf[0][kb+1][lrow]    = rbf.y; Bf[0][kb+2][lrow]    = rbf.z; Bf[0][kb+3][lrow]    = rbf.w;
        Bc[0][kb+0][lrow]    = rbc.x; Bc[0][kb+1][lrow]    = rbc.y; Bc[0][kb+2][lrow]    = rbc.z; Bc[0][kb+3][lrow]    = rbc.w;
    }
    __syncthreads();

    #pragma unroll 1
    for (int c = 0; c < 16; ++c) {
        const int p = c & 1;
        if (c < 15) {
            int kc0 = (c + 1) * 16;
            ra0 = *reinterpret_cast<const float4*>(&hin [(bm + lrow)      * H_DIM + kc0 + lseg * 4]);
            ra1 = *reinterpret_cast<const float4*>(&hin [(bm + lrow + 32) * H_DIM + kc0 + lseg * 4]);
            rbf = *reinterpret_cast<const float4*>(&W_fh[(bn + lrow)      * H_DIM + kc0 + lseg * 4]);
            rbc = *reinterpret_cast<const float4*>(&W_ch[(bn + lrow)      * H_DIM + kc0 + lseg * 4]);
        }
        #pragma unroll
        for (int kk = 0; kk < 16; ++kk) {
            float a[4];
            *reinterpret_cast<float4*>(a) = *reinterpret_cast<const float4*>(&As[p][kk][m0]);
            // Bf/Bc rows are N-contiguous: one 16B LDS yields two packed f32x2
            ulonglong2 ff = *reinterpret_cast<const ulonglong2*>(&Bf[p][kk][n0]);
            ulonglong2 gg = *reinterpret_cast<const ulonglong2*>(&Bc[p][kk][n0]);
            #pragma unroll
            for (int i = 0; i < 4; ++i) {
                u64 aa = pack2(a[i]);
                u2[i][0] = ffma2(aa, ff.x, u2[i][0]);
                u2[i][1] = ffma2(aa, ff.y, u2[i][1]);
                v2[i][0] = ffma2(aa, gg.x, v2[i][0]);
                v2[i][1] = ffma2(aa, gg.y, v2[i][1]);
            }
        }
        if (c < 15) {
            const int q = p ^ 1;     // chunk c-1's buffer: already fully consumed
            int kb = lseg * 4;
            As[q][kb+0][lrow]    = ra0.x; As[q][kb+1][lrow]    = ra0.y; As[q][kb+2][lrow]    = ra0.z; As[q][kb+3][lrow]    = ra0.w;
            As[q][kb+0][lrow+32] = ra1.x; As[q][kb+1][lrow+32] = ra1.y; As[q][kb+2][lrow+32] = ra1.z; As[q][kb+3][lrow+32] = ra1.w;
            Bf[q][kb+0][lrow]    = rbf.x; Bf[q][kb+1][lrow]    = rbf.y; Bf[q][kb+2][lrow]    = rbf.z; Bf[q][kb+3][lrow]    = rbf.w;
            Bc[q][kb+0][lrow]    = rbc.x; Bc[q][kb+1][lrow]    = rbc.y; Bc[q][kb+2][lrow]    = rbc.z; Bc[q][kb+3][lrow]    = rbc.w;
        }
        __syncthreads();
    }

    // ---- fused gate epilogue ----
    float bfh[4], bch[4];
    *reinterpret_cast<float4*>(bfh) = *reinterpret_cast<const float4*>(&b_fh[bn + n0]);
    *reinterpret_cast<float4*>(bch) = *reinterpret_cast<const float4*>(&b_ch[bn + n0]);

    float* hseq = out + (size_t)t * NELEM;
    const int last = (t == S_LEN - 1);

    #pragma unroll
    for (int i = 0; i < 4; ++i) {
        const int m  = bm + m0 + i;
        const int bb = m & (B_SZ - 1);          // batch index (m = s*B + b)
        const int off = m * H_DIM + bn + n0;

        float fx4[4], cx4[4], cc4[4];
        *reinterpret_cast<float4*>(fx4) = *reinterpret_cast<const float4*>(&g_fx[(t * B_SZ + bb) * H_DIM + bn + n0]);
        *reinterpret_cast<float4*>(cx4) = *reinterpret_cast<const float4*>(&g_cx[off]);
        *reinterpret_cast<float4*>(cc4) = *reinterpret_cast<const float4*>(&g_cc[off]);

        float2 u01 = unpack2(u2[i][0]);
        float2 u23 = unpack2(u2[i][1]);
        float2 v01 = unpack2(v2[i][0]);
        float2 v23 = unpack2(v2[i][1]);
        float uu[4] = {u01.x, u01.y, u23.x, u23.y};
        float vv[4] = {v01.x, v01.y, v23.x, v23.y};

        float hn[4], cn[4];
        #pragma unroll
        for (int j = 0; j < 4; ++j) {
            float gate = fast_sigmoid(fx4[j] + uu[j] + bfh[j]);
            float cand = fast_tanh(cx4[j] + vv[j] + bch[j]);
            float c2   = gate * (cc4[j] + cand);   // forget gate == input gate (ref bug)
            cn[j] = c2;
            hn[j] = gate * fast_tanh(c2);          // output gate == g (ref bug)
        }
        *reinterpret_cast<float4*>(&g_cc[off]) = *reinterpret_cast<float4*>(cn);
        *reinterpret_cast<float4*>(&hout[off]) = *reinterpret_cast<float4*>(hn);
        *reinterpret_cast<float4*>(&hseq[off]) = *reinterpret_cast<float4*>(hn);
        if (last) {
            // h_fin == h_seq[S-1], c_fin == final cc
            *reinterpret_cast<float4*>(&out[(size_t)S_LEN * NELEM + off])       = *reinterpret_cast<float4*>(hn);
            *reinterpret_cast<float4*>(&out[(size_t)(S_LEN + 1) * NELEM + off]) = *reinterpret_cast<float4*>(cn);
        }
    }
}

// ---------------------------------------------------------------------------
// Launch: init -> input projections -> 96 sequential fused steps.
// Inputs (metadata order): x, W_fx, b_fx, W_fh, b_fh, W_cx, b_cx, W_ch, b_ch
// Output: [h_seq (S,S,B,H) | h_fin (S,B,H) | c_fin (S,B,H)] flattened.
// ---------------------------------------------------------------------------
extern "C" void kernel_launch(void* const* d_in, const int* in_sizes, int n_in,
                              void* d_out, int out_size)
{
    const float* x    = (const float*)d_in[0];
    const float* W_fx = (const float*)d_in[1];
    const float* b_fx = (const float*)d_in[2];
    const float* W_fh = (const float*)d_in[3];
    const float* b_fh = (const float*)d_in[4];
    const float* W_cx = (const float*)d_in[5];
    const float* b_cx = (const float*)d_in[6];
    const float* W_ch = (const float*)d_in[7];
    const float* b_ch = (const float*)d_in[8];
    float* out = (float*)d_out;

    zero_kernel<<<(NELEM / 4 + 255) / 256, 256>>>();
    pre_kernel<<<dim3(M_ALL / 64, H_DIM / 64), 256>>>(x, W_fx, b_fx, W_cx, b_cx);

    dim3 grid(M_ALL / 64, H_DIM / 32);   // 48 x 8 = 384 CTAs
    for (int t = 0; t < S_LEN; ++t) {
        step_kernel<<<grid, 128>>>(W_fh, b_fh, W_ch, b_ch, out, t);
    }
}